// round 7
// baseline (speedup 1.0000x reference)
#include <cuda_runtime.h>
#include <cuda_fp16.h>
#include <cstdint>
#include <cstddef>

#define NTHREADS 512

// ---------------------------------------------------------------------------
// Shared memory. Gate weights live in REGISTERS (64 uint32/thread @512 thr);
// smem holds the time-invariant attention precompute P, activations, and
// cluster-exchange buffers. `stage` is prologue-only scratch.
// Bank design (4B banks, stride mod 32):
//  - P stride 68  (68 == 4 mod 32): pe stage lane (j=tid>>2,q=tid&3) reads
//    word 68j+q+4i -> bank 4j+q+4i, bijective over the warp. conflict-free.
//  - X stride 34  (== 2 mod 32): ctx lane (e=tid>>4,jj=tid&15) reads word
//    34j+e -> bank 2jj+e; lanes 0-15 even+e, 16-31 odd+e. conflict-free.
//  - W1h half2 stride 132 (== 4 mod 32): Q lane (kk=tid>>3,s=tid&7) reads
//    word 132kk+s+8i -> bank 4kk+s+8i, bijective. conflict-free.
// ---------------------------------------------------------------------------
struct __align__(16) Smem {
    float P[128 * 68];      // [j][kk] x-part of fcEnergy L1 (+b1), our 64-kk slice
    float X[128 * 34];      // [j][e]  x e-slice (32 cols) for context
    float PE[1024];         // [src_rank][j] partial energies
    float Hc[512];          // double-buffered hidden state [2][256]
    float Ctx[256];         // gathered context
    float Qv[64];           // h-part of L1 preact for our kk slice
    float W2s[64];          // W2 slice
    float G[128];           // gate preactivations
    float Bias[128];        // bih+bhh for our rows
    float Wgt[128];         // softmax weights (written redundantly per warp)
    float Hnew[32];         // new h slice (scatter staging)
    float padf[8];
    __half W1h[64 * 264];   // [kk][hh] fp16 W1 h-part slice (fp32 W1 staging in prologue)
    float stage[128 * 260]; // prologue x staging (260 == 4 mod 32)
};
// total = 228,512 B  (< 232,448 max dynamic smem)

__device__ __forceinline__ uint32_t s2u(const void* p) {
    uint32_t a;
    asm("{ .reg .u64 t; cvta.to.shared.u64 t, %1; cvt.u32.u64 %0, t; }"
        : "=r"(a) : "l"(p));
    return a;
}
__device__ __forceinline__ void stc(uint32_t addr, uint32_t rank, float v) {
    uint32_t r;
    asm volatile("mapa.shared::cluster.u32 %0, %1, %2;" : "=r"(r) : "r"(addr), "r"(rank));
    asm volatile("st.shared::cluster.f32 [%0], %1;" :: "r"(r), "f"(v) : "memory");
}
__device__ __forceinline__ void cluster_arrive() {
    asm volatile("barrier.cluster.arrive.aligned;" ::: "memory");
}
__device__ __forceinline__ void cluster_wait() {
    asm volatile("barrier.cluster.wait.aligned;" ::: "memory");
}
__device__ __forceinline__ float tanh_fast(float x) {
    float y; asm("tanh.approx.f32 %0, %1;" : "=f"(y) : "f"(x)); return y;
}
__device__ __forceinline__ float sigm(float x) { return 1.f / (1.f + __expf(-x)); }

__global__ void __cluster_dims__(8, 1, 1) __launch_bounds__(NTHREADS, 1)
lstm_attn_kernel(const float* __restrict__ gx, const int* __restrict__ gseq,
                 const float* __restrict__ gW1, const float* __restrict__ gb1,
                 const float* __restrict__ gW2, const float* __restrict__ gb2,
                 const float* __restrict__ gWih, const float* __restrict__ gWhh,
                 const float* __restrict__ gbih, const float* __restrict__ gbhh,
                 float* __restrict__ out)
{
    extern __shared__ char smraw[];
    Smem& sm = *reinterpret_cast<Smem*>(smraw);
    const int tid = (int)threadIdx.x;
    const int b   = (int)blockIdx.x >> 3;   // batch = cluster id
    const int c   = (int)blockIdx.x & 7;    // rank within cluster
    const int len = gseq[b];

    float* outO = out;                      // outputs  [8][128][256]
    float* outL = out + 262144;             // seq_lengths [8]
    float* outH = out + 262152;             // hidden   [1][8][256]
    float* outA = out + 264200;             // attn     [8][128][128]

    // ---------------- prologue ----------------
    sm.Hc[tid] = 0.f;                       // 512 threads: both buffers

    {   // zero padded output rows (d_out is poisoned)
        const int padT = 128 - len;
        for (int idx = (c << 9) + tid; idx < padT * 256; idx += 4096)
            outO[(size_t)b * 32768 + (size_t)len * 256 + idx] = 0.f;
        for (int idx = (c << 9) + tid; idx < padT * 128; idx += 4096)
            outA[(size_t)b * 16384 + (size_t)len * 128 + idx] = 0.f;
        if (c == 0 && tid == 0) outL[b] = (float)len;
    }

    // stage x[b] (fp32), stride 260
    for (int idx = tid; idx < 128 * 256; idx += NTHREADS) {
        int j = idx >> 8, e = idx & 255;
        sm.stage[j * 260 + e] = gx[(size_t)b * 32768 + idx];
    }
    __syncthreads();

    // P[j][kk] = x[b,j,:] . W1[c*64+kk, :256] + b1   (two kk-passes of 32)
    // thread = (j = tid>>2, q = tid&3); q owns e in [64q, 64q+64), x in regs.
    const int jP = tid >> 2, qP = tid & 3;
    {
        float4 xr4[16];
        #pragma unroll
        for (int i = 0; i < 16; ++i)
            xr4[i] = *reinterpret_cast<const float4*>(&sm.stage[jP * 260 + qP * 64 + 4 * i]);

        float* wst = reinterpret_cast<float*>(sm.W1h);  // fp32 staging, stride 260
        for (int pass = 0; pass < 2; ++pass) {
            __syncthreads();                            // prior P writes done before restage
            for (int idx = tid; idx < 32 * 256; idx += NTHREADS) {
                int row = idx >> 8, e = idx & 255;
                wst[row * 260 + e] = gW1[(size_t)(c * 64 + pass * 32 + row) * 512 + e];
            }
            __syncthreads();
            for (int blk = 0; blk < 4; ++blk) {
                float acc[8];
                #pragma unroll
                for (int r = 0; r < 8; ++r) acc[r] = 0.f;
                const float* wb = wst + (blk * 8) * 260 + qP * 64;
                #pragma unroll 4
                for (int i = 0; i < 16; ++i) {
                    float4 xv = xr4[i];
                    #pragma unroll
                    for (int r = 0; r < 8; ++r) {
                        float4 wv = *reinterpret_cast<const float4*>(wb + r * 260 + 4 * i);
                        acc[r] = fmaf(xv.x, wv.x, acc[r]);
                        acc[r] = fmaf(xv.y, wv.y, acc[r]);
                        acc[r] = fmaf(xv.z, wv.z, acc[r]);
                        acc[r] = fmaf(xv.w, wv.w, acc[r]);
                    }
                }
                #pragma unroll
                for (int r = 0; r < 8; ++r) {
                    float o = acc[r];
                    o += __shfl_xor_sync(0xffffffffu, o, 1);
                    o += __shfl_xor_sync(0xffffffffu, o, 2);
                    if (qP == 0) {
                        const int kk = pass * 32 + blk * 8 + r;
                        sm.P[jP * 68 + kk] = o + gb1[c * 64 + kk];
                    }
                }
            }
        }
        __syncthreads();
    }

    // X e-slice for context
    for (int idx = tid; idx < 128 * 32; idx += NTHREADS) {
        int j = idx >> 5, e = idx & 31;
        sm.X[j * 34 + e] = sm.stage[j * 260 + c * 32 + e];
    }
    __syncthreads();                         // stage/wst reads done

    // W1 h-part slice -> fp16 (overwrites its own fp32 staging)
    for (int idx = tid; idx < 64 * 128; idx += NTHREADS) {
        int kk = idx >> 7, i = idx & 127;
        float2 v = *reinterpret_cast<const float2*>(gW1 + (size_t)(c * 64 + kk) * 512 + 256 + 2 * i);
        reinterpret_cast<__half2*>(sm.W1h)[kk * 132 + i] = __floats2half2_rn(v.x, v.y);
    }
    if (tid < 64) sm.W2s[tid] = gW2[c * 64 + tid];
    if (tid < 128) {
        int g = tid >> 5, uu = tid & 31;
        sm.Bias[tid] = gbih[g * 256 + c * 32 + uu] + gbhh[g * 256 + c * 32 + uu];
    }

    // ---- gate weights into REGISTERS: row r = tid>>2, quarter p = tid&3 ----
    const int r_row = tid >> 2, p = tid & 3;
    uint32_t wih_r[32], whh_r[32];
    {
        const int grow = (r_row >> 5) * 256 + c * 32 + (r_row & 31);
        const float* bih_ = gWih + (size_t)grow * 256 + (p << 6);
        const float* bhh_ = gWhh + (size_t)grow * 256 + (p << 6);
        #pragma unroll
        for (int i = 0; i < 32; ++i) {
            float2 v = *reinterpret_cast<const float2*>(bih_ + 2 * i);
            __half2 h2 = __floats2half2_rn(v.x, v.y);
            wih_r[i] = *reinterpret_cast<uint32_t*>(&h2);
        }
        #pragma unroll
        for (int i = 0; i < 32; ++i) {
            float2 v = *reinterpret_cast<const float2*>(bhh_ + 2 * i);
            __half2 h2 = __floats2half2_rn(v.x, v.y);
            whh_r[i] = *reinterpret_cast<uint32_t*>(&h2);
        }
    }
    __syncthreads();
    cluster_arrive(); cluster_wait();

    const float b2v = gb2[0];
    const uint32_t peAddr  = s2u(sm.PE);
    const uint32_t ctxAddr = s2u(sm.Ctx);
    const uint32_t hcAddr  = s2u(sm.Hc);
    const int lane = tid & 31;

    float creg = 0.f, hlast = 0.f;          // per-unit state (threads 0..31)

    // ---------------- time loop (only observable steps) ----------------
    for (int t = 0; t < len; ++t) {
        const float* Hcur = sm.Hc + (t & 1) * 256;

        // ---- Q[kk] = h . W1h[kk,:]   (kk = tid>>3, s = tid&7) ----
        {
            const int kk = tid >> 3, s = tid & 7;
            const __half2* wr = reinterpret_cast<const __half2*>(sm.W1h) + kk * 132 + s;
            const float2* h2 = reinterpret_cast<const float2*>(Hcur) + s;
            float acc = 0.f;
            #pragma unroll
            for (int i = 0; i < 16; ++i) {
                float2 w = __half22float2(wr[8 * i]);
                float2 h = h2[8 * i];
                acc = fmaf(w.x, h.x, acc);
                acc = fmaf(w.y, h.y, acc);
            }
            acc += __shfl_xor_sync(0xffffffffu, acc, 1);
            acc += __shfl_xor_sync(0xffffffffu, acc, 2);
            acc += __shfl_xor_sync(0xffffffffu, acc, 4);
            if (s == 0) sm.Qv[kk] = acc;
        }
        __syncthreads();

        // ---- partial energies: pe[j] = sum_kk tanh(P+Q)*W2 (j=tid>>2,q=tid&3) ----
        {
            const int j = tid >> 2, q = tid & 3;
            float acc = 0.f;
            #pragma unroll
            for (int i = 0; i < 16; ++i) {
                int kk = q + 4 * i;
                float v = sm.P[j * 68 + kk] + sm.Qv[kk];
                acc = fmaf(tanh_fast(v), sm.W2s[kk], acc);
            }
            acc += __shfl_xor_sync(0xffffffffu, acc, 1);
            acc += __shfl_xor_sync(0xffffffffu, acc, 2);
            if (q == 0) {
                uint32_t a = peAddr + (uint32_t)((c * 128 + j) * 4);
                #pragma unroll
                for (int rr = 0; rr < 8; ++rr) stc(a, rr, acc);
            }
        }
        cluster_arrive();   // B1 arrive: PE in flight

        // ---- hidden behind B1: Whh part of the gates (indep. of PE) ----
        float a_hh;
        {
            float a0 = 0.f, a1 = 0.f;
            const float4* h4 = reinterpret_cast<const float4*>(Hcur + (p << 6));
            #pragma unroll
            for (int i = 0; i < 16; ++i) {
                float4 v = h4[i];
                float2 w0 = __half22float2(*reinterpret_cast<const __half2*>(&whh_r[2 * i]));
                float2 w1 = __half22float2(*reinterpret_cast<const __half2*>(&whh_r[2 * i + 1]));
                a0 = fmaf(w0.x, v.x, a0); a1 = fmaf(w0.y, v.y, a1);
                a0 = fmaf(w1.x, v.z, a0); a1 = fmaf(w1.y, v.w, a1);
            }
            a_hh = a0 + a1;
        }
        cluster_wait();     // B1 wait: PE ready everywhere

        // ---- warp-local softmax (each warp computes all 128 j's, no syncs) ----
        {
            float e[4];
            #pragma unroll
            for (int qd = 0; qd < 4; ++qd) {
                const int j = lane + 32 * qd;
                float s = 0.f;
                #pragma unroll
                for (int rr = 0; rr < 8; ++rr) s += sm.PE[rr * 128 + j];
                e[qd] = (j < len) ? tanhf(s + b2v) : -1e30f;
            }
            float m = fmaxf(fmaxf(e[0], e[1]), fmaxf(e[2], e[3]));
            #pragma unroll
            for (int o = 16; o; o >>= 1) m = fmaxf(m, __shfl_xor_sync(0xffffffffu, m, o));
            float w[4], ssum = 0.f;
            #pragma unroll
            for (int qd = 0; qd < 4; ++qd) { w[qd] = __expf(e[qd] - m); ssum += w[qd]; }
            #pragma unroll
            for (int o = 16; o; o >>= 1) ssum += __shfl_xor_sync(0xffffffffu, ssum, o);
            const float inv = 1.f / ssum;
            #pragma unroll
            for (int qd = 0; qd < 4; ++qd) {
                w[qd] *= inv;
                sm.Wgt[lane + 32 * qd] = w[qd];     // identical values from all warps
            }
            if (c == 0 && tid < 32) {
                float* row = outA + (size_t)(b * 128 + t) * 128;
                #pragma unroll
                for (int qd = 0; qd < 4; ++qd) row[lane + 32 * qd] = w[qd];
            }
        }
        __syncwarp();

        // ---- context slice: e = tid>>4 (32 e), jj = tid&15 ----
        {
            const int e = tid >> 4, jj = tid & 15;
            float acc = 0.f;
            #pragma unroll
            for (int mm = 0; mm < 8; ++mm) {
                int j = jj + 16 * mm;
                acc = fmaf(sm.Wgt[j], sm.X[j * 34 + e], acc);
            }
            acc += __shfl_xor_sync(0xffffffffu, acc, 1);
            acc += __shfl_xor_sync(0xffffffffu, acc, 2);
            acc += __shfl_xor_sync(0xffffffffu, acc, 4);
            acc += __shfl_xor_sync(0xffffffffu, acc, 8);
            if (jj == 0) {
                uint32_t a = ctxAddr + (uint32_t)((c * 32 + e) * 4);
                #pragma unroll
                for (int rr = 0; rr < 8; ++rr) stc(a, rr, acc);
            }
        }
        cluster_arrive();   // B2 arrive: Ctx in flight
        cluster_wait();     // B2 wait: Ctx ready everywhere

        // ---- Wih part of gates + reduce (a_hh already computed) ----
        {
            float a0 = a_hh, a1 = 0.f;
            const float4* c4 = reinterpret_cast<const float4*>(sm.Ctx + (p << 6));
            #pragma unroll
            for (int i = 0; i < 16; ++i) {
                float4 v = c4[i];
                float2 w0 = __half22float2(*reinterpret_cast<const __half2*>(&wih_r[2 * i]));
                float2 w1 = __half22float2(*reinterpret_cast<const __half2*>(&wih_r[2 * i + 1]));
                a0 = fmaf(w0.x, v.x, a0); a1 = fmaf(w0.y, v.y, a1);
                a0 = fmaf(w1.x, v.z, a0); a1 = fmaf(w1.y, v.w, a1);
            }
            float acc = a0 + a1;
            acc += __shfl_xor_sync(0xffffffffu, acc, 1);
            acc += __shfl_xor_sync(0xffffffffu, acc, 2);
            if (p == 0) sm.G[r_row] = acc + sm.Bias[r_row];
        }
        __syncthreads();

        // ---- state update (32 units per CTA) ----
        if (tid < 32) {
            float gi = sm.G[tid],      gf = sm.G[32 + tid];
            float gg = sm.G[64 + tid], go = sm.G[96 + tid];
            creg = sigm(gf) * creg + sigm(gi) * tanhf(gg);
            float hn = sigm(go) * tanhf(creg);
            if (t == len - 1) hlast = hn;
            outO[(size_t)(b * 128 + t) * 256 + (c * 32 + tid)] = hn;
            sm.Hnew[tid] = hn;
        }
        __syncthreads();

        // ---- all-gather h into the NEXT Hc buffer (threads 0..255) ----
        if (tid < 256) {
            const int rk = tid >> 5, uu = tid & 31;
            uint32_t a = hcAddr + (uint32_t)(((((t + 1) & 1) * 256) + c * 32 + uu) * 4);
            stc(a, rk, sm.Hnew[uu]);
        }
        cluster_arrive();   // B3
        cluster_wait();     // h ready for step t+1
    }

    if (tid < 32)
        outH[(size_t)b * 256 + c * 32 + tid] = hlast;
}

extern "C" void kernel_launch(void* const* d_in, const int* in_sizes, int n_in,
                              void* d_out, int out_size) {
    (void)in_sizes; (void)n_in; (void)out_size;
    const float* x    = (const float*)d_in[0];
    const int*   seq  = (const int*)d_in[1];
    const float* W1   = (const float*)d_in[2];
    const float* b1   = (const float*)d_in[3];
    const float* W2   = (const float*)d_in[4];
    const float* b2   = (const float*)d_in[5];
    const float* Wih  = (const float*)d_in[6];
    const float* Whh  = (const float*)d_in[7];
    const float* bih  = (const float*)d_in[8];
    const float* bhh  = (const float*)d_in[9];
    float* out = (float*)d_out;

    cudaFuncSetAttribute(lstm_attn_kernel,
                         cudaFuncAttributeMaxDynamicSharedMemorySize,
                         (int)sizeof(Smem));
    lstm_attn_kernel<<<64, NTHREADS, sizeof(Smem)>>>(
        x, seq, W1, b1, W2, b2, Wih, Whh, bih, bhh, out);
}

// round 8
// speedup vs baseline: 1.7019x; 1.7019x over previous
#include <cuda_runtime.h>
#include <cuda_fp16.h>
#include <cstdint>
#include <cstddef>

#define NTHREADS 256

#define FMA_F32X2(d, a, b, c) \
    asm("fma.rn.f32x2 %0, %1, %2, %3;" : "=l"(d) : "l"(a), "l"(b), "l"(c))
#define PACK2(d, lo, hi) \
    asm("mov.b64 %0, {%1, %2};" : "=l"(d) : "f"(lo), "f"(hi))
#define UNPACK2(lo, hi, s) \
    asm("mov.b64 {%0, %1}, %2;" : "=f"(lo), "=f"(hi) : "l"(s))

// ---------------------------------------------------------------------------
// Smem. Gate Whh weights live in REGISTERS (64 uint32/thread, 256 thr).
// Gx[row][j] = Wih_row . x_j (fp32) makes the Wih gate half a dot against the
// softmax weights -> the context exchange barrier (B2) is eliminated.
// Bank design (word = 4B, banks mod 32):
//  - P stride 66 (== 2 mod 32): pe lane (j=tid>>1,q=tid&1) word 66j+q+2i ->
//    bank 2j+q+2i, bijective. conflict-free.
//  - Gx stride 130 (== 2), p-offset 65 (odd): gates lane (r=tid>>1,p=tid&1)
//    word 130r+65p+i -> bank 2r+p+i, bijective. conflict-free.
//  - W1h half2 stride 132 (== 4): Q lane (kk=tid>>2,q=tid&3) word 132kk+q+4i
//    -> bank 4kk+q+4i, bijective. conflict-free.
//  - Wgt padded (word = j + (j>>6)): gates_x reads j=64p+i -> 2 distinct
//    addresses on 2 distinct banks, broadcast within p-group. conflict-free.
//  - prologue wst stride 272, quarter-offset 68: LDS.128 word 272r+68q+4i ->
//    4 addresses, banks {16r+4q+4i} distinct. conflict-free.
// ---------------------------------------------------------------------------
struct __align__(16) Smem {
    float P[128 * 66];     // [j][kk] x-part of fcEnergy L1 (+b1), our 64-kk slice
    float Gx[128 * 130];   // [row][j]: j<64 at +j, j>=64 at +65+(j-64)
    float PE[1024];        // [src_rank][j] partial energies
    float Hc[512];         // double-buffered hidden state [2][256]
    float Qv[64];          // h-part of L1 preact for our kk slice
    float W2s[64];         // W2 slice
    float G[128];          // gate preactivations
    float Bias[128];       // bih+bhh for our rows
    float Wgt[132];        // softmax weights, padded (word = j + (j>>6))
    float Hnew[32];        // new h slice (scatter staging)
    float padf[4];
    __half W1h[64 * 264];  // [kk][hh] fp16 W1 h-part; fp32 W staging in prologue
};
// total = 142,496 B  (< 232,448 max dynamic smem)

__device__ __forceinline__ uint32_t s2u(const void* p) {
    uint32_t a;
    asm("{ .reg .u64 t; cvta.to.shared.u64 t, %1; cvt.u32.u64 %0, t; }"
        : "=r"(a) : "l"(p));
    return a;
}
__device__ __forceinline__ void stc(uint32_t addr, uint32_t rank, float v) {
    uint32_t r;
    asm volatile("mapa.shared::cluster.u32 %0, %1, %2;" : "=r"(r) : "r"(addr), "r"(rank));
    asm volatile("st.shared::cluster.f32 [%0], %1;" :: "r"(r), "f"(v) : "memory");
}
__device__ __forceinline__ void cluster_arrive() {
    asm volatile("barrier.cluster.arrive.aligned;" ::: "memory");
}
__device__ __forceinline__ void cluster_wait() {
    asm volatile("barrier.cluster.wait.aligned;" ::: "memory");
}
__device__ __forceinline__ float tanh_fast(float x) {   // MUFU, inner hdn only
    float y; asm("tanh.approx.f32 %0, %1;" : "=f"(y) : "f"(x)); return y;
}
__device__ __forceinline__ float tanh_acc(float x) {    // ~1e-6 err, ~5 instr
    float e = __expf(2.f * x);
    return 1.f - __fdividef(2.f, e + 1.f);
}
__device__ __forceinline__ float sigm(float x) { return 1.f / (1.f + __expf(-x)); }

__global__ void __cluster_dims__(8, 1, 1) __launch_bounds__(NTHREADS, 1)
lstm_attn_kernel(const float* __restrict__ gx, const int* __restrict__ gseq,
                 const float* __restrict__ gW1, const float* __restrict__ gb1,
                 const float* __restrict__ gW2, const float* __restrict__ gb2,
                 const float* __restrict__ gWih, const float* __restrict__ gWhh,
                 const float* __restrict__ gbih, const float* __restrict__ gbhh,
                 float* __restrict__ out)
{
    extern __shared__ char smraw[];
    Smem& sm = *reinterpret_cast<Smem*>(smraw);
    const int tid = (int)threadIdx.x;
    const int b   = (int)blockIdx.x >> 3;   // batch = cluster id
    const int c   = (int)blockIdx.x & 7;    // rank within cluster
    const int len = gseq[b];
    const int lane = tid & 31;

    float* outO = out;                      // outputs  [8][128][256]
    float* outL = out + 262144;             // seq_lengths [8]
    float* outH = out + 262152;             // hidden   [1][8][256]
    float* outA = out + 264200;             // attn     [8][128][128]

    // ---------------- prologue ----------------
    sm.Hc[tid] = 0.f; sm.Hc[256 + tid] = 0.f;

    {   // zero padded output rows (d_out is poisoned)
        const int padT = 128 - len;
        for (int idx = (c << 8) + tid; idx < padT * 256; idx += 2048)
            outO[(size_t)b * 32768 + (size_t)len * 256 + idx] = 0.f;
        for (int idx = (c << 8) + tid; idx < padT * 128; idx += 2048)
            outA[(size_t)b * 16384 + (size_t)len * 128 + idx] = 0.f;
        if (c == 0 && tid == 0) outL[b] = (float)len;
    }

    // Unified prologue GEMM: 192 W-rows (64 -> P slice, 128 -> Gx) x 128 x_j.
    // 12 passes of 16 rows staged fp32 into the W1h area; x read from L1.
    {
        const int jq = tid >> 2;            // 0..63
        const int qq = tid & 3;             // e-quarter
        float* wst = reinterpret_cast<float*>(sm.W1h);  // 16 x 272 floats

        for (int pass = 0; pass < 12; ++pass) {
            __syncthreads();                // prior-pass wst reads complete
            for (int i = tid; i < 16 * 256; i += NTHREADS) {
                int r = i >> 8, e = i & 255;
                int row = pass * 16 + r;
                float v;
                if (row < 64) {
                    v = gW1[(size_t)(c * 64 + row) * 512 + e];
                } else {
                    int idx = row - 64, g = idx >> 5, u = idx & 31;
                    v = gWih[(size_t)(g * 256 + c * 32 + u) * 256 + e];
                }
                wst[r * 272 + (e >> 6) * 68 + (e & 63)] = v;
            }
            __syncthreads();

            for (int jb = 0; jb < 2; ++jb) {
                const int j = jb * 64 + jq;
                unsigned long long xp[32];
                const float* xrow = gx + (size_t)b * 32768 + (size_t)j * 256 + qq * 64;
                #pragma unroll
                for (int i = 0; i < 16; ++i) {
                    float4 v = *reinterpret_cast<const float4*>(xrow + 4 * i);
                    PACK2(xp[2 * i],     v.x, v.y);
                    PACK2(xp[2 * i + 1], v.z, v.w);
                }
                #pragma unroll 2
                for (int r = 0; r < 16; ++r) {
                    const float4* wr = reinterpret_cast<const float4*>(wst + r * 272 + qq * 68);
                    unsigned long long acc0, acc1;
                    PACK2(acc0, 0.f, 0.f);
                    PACK2(acc1, 0.f, 0.f);
                    #pragma unroll
                    for (int i = 0; i < 16; ++i) {
                        float4 w = wr[i];
                        unsigned long long w0, w1;
                        PACK2(w0, w.x, w.y);
                        PACK2(w1, w.z, w.w);
                        FMA_F32X2(acc0, xp[2 * i],     w0, acc0);
                        FMA_F32X2(acc1, xp[2 * i + 1], w1, acc1);
                    }
                    float l0, h0, l1, h1;
                    UNPACK2(l0, h0, acc0);
                    UNPACK2(l1, h1, acc1);
                    float s = (l0 + h0) + (l1 + h1);
                    s += __shfl_xor_sync(0xffffffffu, s, 1);
                    s += __shfl_xor_sync(0xffffffffu, s, 2);
                    if (qq == 0) {
                        int row = pass * 16 + r;
                        if (row < 64)
                            sm.P[j * 66 + row] = s + gb1[c * 64 + row];
                        else {
                            int idx = row - 64;
                            sm.Gx[idx * 130 + (j < 64 ? j : 65 + (j - 64))] = s;
                        }
                    }
                }
            }
        }
        __syncthreads();                    // last-pass wst reads complete
    }

    // W1 h-part slice -> fp16 (overwrites the staging area)
    for (int i = tid; i < 64 * 128; i += NTHREADS) {
        int kk = i >> 7, hh = i & 127;
        float2 v = *reinterpret_cast<const float2*>(gW1 + (size_t)(c * 64 + kk) * 512 + 256 + 2 * hh);
        reinterpret_cast<__half2*>(sm.W1h)[kk * 132 + hh] = __floats2half2_rn(v.x, v.y);
    }
    if (tid < 64) sm.W2s[tid] = gW2[c * 64 + tid];
    if (tid < 128) {
        int g = tid >> 5, uu = tid & 31;
        sm.Bias[tid] = gbih[g * 256 + c * 32 + uu] + gbhh[g * 256 + c * 32 + uu];
    }

    // ---- Whh gate weights into REGISTERS: row r = tid>>1, half p = tid&1 ----
    const int r_row = tid >> 1, p = tid & 1;
    uint32_t whh_r[64];
    {
        const int grow = (r_row >> 5) * 256 + c * 32 + (r_row & 31);
        const float* bhh_ = gWhh + (size_t)grow * 256 + (p << 7);
        #pragma unroll
        for (int i = 0; i < 64; ++i) {
            float2 v = *reinterpret_cast<const float2*>(bhh_ + 2 * i);
            __half2 h2 = __floats2half2_rn(v.x, v.y);
            whh_r[i] = *reinterpret_cast<uint32_t*>(&h2);
        }
    }
    __syncthreads();
    cluster_arrive(); cluster_wait();

    const float b2v = gb2[0];
    const uint32_t peAddr = s2u(sm.PE);
    const uint32_t hcAddr = s2u(sm.Hc);

    float creg = 0.f, hlast = 0.f;          // per-unit state (threads 0..31)

    // ---------------- time loop (only observable steps) ----------------
    for (int t = 0; t < len; ++t) {
        const float* Hcur = sm.Hc + (t & 1) * 256;

        // ---- Q[kk] = h . W1h[kk,:]   (kk = tid>>2, q = tid&3) ----
        {
            const int kk = tid >> 2, q = tid & 3;
            const __half2* wr = reinterpret_cast<const __half2*>(sm.W1h) + kk * 132 + q;
            const float2* h2 = reinterpret_cast<const float2*>(Hcur) + q;
            float a0 = 0.f, a1 = 0.f;
            #pragma unroll
            for (int i = 0; i < 32; i += 2) {
                float2 w = __half22float2(wr[4 * i]);
                float2 h = h2[4 * i];
                a0 = fmaf(w.x, h.x, a0); a0 = fmaf(w.y, h.y, a0);
                float2 w2 = __half22float2(wr[4 * i + 4]);
                float2 hb = h2[4 * i + 4];
                a1 = fmaf(w2.x, hb.x, a1); a1 = fmaf(w2.y, hb.y, a1);
            }
            float acc = a0 + a1;
            acc += __shfl_xor_sync(0xffffffffu, acc, 1);
            acc += __shfl_xor_sync(0xffffffffu, acc, 2);
            if (q == 0) sm.Qv[kk] = acc;
        }
        __syncthreads();

        // ---- partial energies: pe[j] = sum_kk tanh(P+Q)*W2 ----
        {
            const int j = tid >> 1, q = tid & 1;
            float acc = 0.f;
            #pragma unroll
            for (int i = 0; i < 32; ++i) {
                int kk = q + 2 * i;
                float v = sm.P[j * 66 + kk] + sm.Qv[kk];
                acc = fmaf(tanh_fast(v), sm.W2s[kk], acc);
            }
            acc += __shfl_xor_sync(0xffffffffu, acc, 1);
            if (q == 0) {
                uint32_t a = peAddr + (uint32_t)((c * 128 + j) * 4);
                #pragma unroll
                for (int rr = 0; rr < 8; ++rr) stc(a, rr, acc);
            }
        }
        cluster_arrive();   // B1 arrive: PE in flight

        // ---- hidden behind B1: Whh half of the gates (indep. of PE) ----
        float a_hh;
        {
            float a0 = 0.f, a1 = 0.f;
            const float4* h4 = reinterpret_cast<const float4*>(Hcur + (p << 7));
            #pragma unroll
            for (int i = 0; i < 32; ++i) {
                float4 v = h4[i];
                float2 w0 = __half22float2(*reinterpret_cast<const __half2*>(&whh_r[2 * i]));
                float2 w1 = __half22float2(*reinterpret_cast<const __half2*>(&whh_r[2 * i + 1]));
                a0 = fmaf(w0.x, v.x, a0); a1 = fmaf(w0.y, v.y, a1);
                a0 = fmaf(w1.x, v.z, a0); a1 = fmaf(w1.y, v.w, a1);
            }
            a_hh = a0 + a1;
        }
        cluster_wait();     // B1 wait: PE ready everywhere

        // ---- warp-local softmax (each warp computes all 128 j's) ----
        {
            float e[4];
            #pragma unroll
            for (int qd = 0; qd < 4; ++qd) {
                const int j = lane + 32 * qd;
                float s = 0.f;
                #pragma unroll
                for (int rr = 0; rr < 8; ++rr) s += sm.PE[rr * 128 + j];
                e[qd] = (j < len) ? tanh_acc(s + b2v) : -1e30f;
            }
            float m = fmaxf(fmaxf(e[0], e[1]), fmaxf(e[2], e[3]));
            #pragma unroll
            for (int o = 16; o; o >>= 1) m = fmaxf(m, __shfl_xor_sync(0xffffffffu, m, o));
            float w[4], ssum = 0.f;
            #pragma unroll
            for (int qd = 0; qd < 4; ++qd) { w[qd] = __expf(e[qd] - m); ssum += w[qd]; }
            #pragma unroll
            for (int o = 16; o; o >>= 1) ssum += __shfl_xor_sync(0xffffffffu, ssum, o);
            const float inv = 1.f / ssum;
            #pragma unroll
            for (int qd = 0; qd < 4; ++qd) {
                w[qd] *= inv;
                const int j = lane + 32 * qd;
                sm.Wgt[j + (j >> 6)] = w[qd];   // identical values from all warps
            }
            if (c == 0 && tid < 32) {
                float* row = outA + (size_t)(b * 128 + t) * 128;
                #pragma unroll
                for (int qd = 0; qd < 4; ++qd) row[lane + 32 * qd] = w[qd];
            }
        }
        __syncwarp();

        // ---- gates: a_hh + sum_j w_j * Gx[row][j]  (no ctx barrier!) ----
        {
            float a0 = a_hh, a1 = 0.f;
            const float* gxr = &sm.Gx[r_row * 130 + 65 * p];
            const float* wv  = &sm.Wgt[65 * p];
            #pragma unroll
            for (int i = 0; i < 64; i += 2) {
                a0 = fmaf(wv[i],     gxr[i],     a0);
                a1 = fmaf(wv[i + 1], gxr[i + 1], a1);
            }
            float acc = a0 + a1;
            acc += __shfl_xor_sync(0xffffffffu, acc, 1);
            if (p == 0) sm.G[r_row] = acc + sm.Bias[r_row];
        }
        __syncthreads();

        // ---- state update (32 units per CTA) ----
        if (tid < 32) {
            float gi = sm.G[tid],      gf = sm.G[32 + tid];
            float gg = sm.G[64 + tid], go = sm.G[96 + tid];
            creg = sigm(gf) * creg + sigm(gi) * tanh_acc(gg);
            float hn = sigm(go) * tanh_acc(creg);
            if (t == len - 1) hlast = hn;
            outO[(size_t)(b * 128 + t) * 256 + (c * 32 + tid)] = hn;
            sm.Hnew[tid] = hn;
        }
        __syncthreads();

        // ---- all-gather h into the NEXT Hc buffer ----
        {
            const int rk = tid >> 5, uu = tid & 31;
            uint32_t a = hcAddr + (uint32_t)(((((t + 1) & 1) * 256) + c * 32 + uu) * 4);
            stc(a, rk, sm.Hnew[uu]);
        }
        cluster_arrive();   // B3
        cluster_wait();     // h ready for step t+1
    }

    if (tid < 32)
        outH[(size_t)b * 256 + c * 32 + tid] = hlast;
}

extern "C" void kernel_launch(void* const* d_in, const int* in_sizes, int n_in,
                              void* d_out, int out_size) {
    (void)in_sizes; (void)n_in; (void)out_size;
    const float* x    = (const float*)d_in[0];
    const int*   seq  = (const int*)d_in[1];
    const float* W1   = (const float*)d_in[2];
    const float* b1   = (const float*)d_in[3];
    const float* W2   = (const float*)d_in[4];
    const float* b2   = (const float*)d_in[5];
    const float* Wih  = (const float*)d_in[6];
    const float* Whh  = (const float*)d_in[7];
    const float* bih  = (const float*)d_in[8];
    const float* bhh  = (const float*)d_in[9];
    float* out = (float*)d_out;

    cudaFuncSetAttribute(lstm_attn_kernel,
                         cudaFuncAttributeMaxDynamicSharedMemorySize,
                         (int)sizeof(Smem));
    lstm_attn_kernel<<<64, NTHREADS, sizeof(Smem)>>>(
        x, seq, W1, b1, W2, b2, Wih, Whh, bih, bhh, out);
}